// round 15
// baseline (speedup 1.0000x reference)
#include <cuda_runtime.h>
#include <cuda_fp16.h>
#include <cstdint>

namespace {
constexpr int BM = 64, BN = 64, DIM = 128;
constexpr int NTHREADS = 128;
constexpr int HEADS = 32, KVH = 8, REP = HEADS / KVH;
constexpr int LD = 136;      // fp16 elems per smem row: 272B stride, conflict-free ldmatrix
constexpr int ROWB = LD * 2; // 272
// 1/sqrt(128) * log2(e): exp(s) == exp2(s') with s' computed from pre-scaled Q
constexpr float SCALE_L2E = 0.12751743136838648f;

constexpr int MAXT = 8192;

// smem: two buffers of [KH, VH]; Q staged through buffer 1 pre-loop
constexpr int TILEB = BN * ROWB;               // 17408
constexpr int BUFSZ = 2 * TILEB;               // 34816
constexpr int SMEM_TOTAL = 2 * BUFSZ;          // 69632 -> 3 CTAs/SM (208896 B)
}  // namespace

// persistent fp16 K/V (elem-pairs as uint32: low 16 = even elem)
__device__ uint32_t g_kh[MAXT * KVH * DIM / 2];
__device__ uint32_t g_vh[MAXT * KVH * DIM / 2];

__device__ __forceinline__ uint32_t smem_u32(const void* p) {
  uint32_t a;
  asm("{ .reg .u64 t; cvta.to.shared.u64 t, %1; cvt.u32.u64 %0, t; }" : "=r"(a) : "l"(p));
  return a;
}
__device__ __forceinline__ uint32_t cvt_h2(float a, float b) {
  uint32_t h;
  asm("cvt.rn.f16x2.f32 %0, %1, %2;" : "=r"(h) : "f"(b), "f"(a));  // low16=a, high16=b
  return h;
}
__device__ __forceinline__ float ex2(float x) {
  float y;
  asm("ex2.approx.ftz.f32 %0, %1;" : "=f"(y) : "f"(x));
  return y;
}
__device__ __forceinline__ void ldsm4(uint32_t a, uint32_t* r) {
  asm volatile("ldmatrix.sync.aligned.m8n8.x4.shared.b16 {%0,%1,%2,%3}, [%4];"
               : "=r"(r[0]), "=r"(r[1]), "=r"(r[2]), "=r"(r[3]) : "r"(a));
}
__device__ __forceinline__ void ldsm4t(uint32_t a, uint32_t* r) {
  asm volatile("ldmatrix.sync.aligned.m8n8.x4.trans.shared.b16 {%0,%1,%2,%3}, [%4];"
               : "=r"(r[0]), "=r"(r[1]), "=r"(r[2]), "=r"(r[3]) : "r"(a));
}
__device__ __forceinline__ void mma_f16(float* c, const uint32_t* a, uint32_t b0,
                                        uint32_t b1) {
  asm volatile(
      "mma.sync.aligned.m16n8k16.row.col.f32.f16.f16.f32 "
      "{%0,%1,%2,%3}, {%4,%5,%6,%7}, {%8,%9}, {%0,%1,%2,%3};"
      : "+f"(c[0]), "+f"(c[1]), "+f"(c[2]), "+f"(c[3])
      : "r"(a[0]), "r"(a[1]), "r"(a[2]), "r"(a[3]), "r"(b0), "r"(b1));
}
__device__ __forceinline__ void cp16(uint32_t dst, const uint32_t* src) {
  asm volatile(
      "{ .reg .u64 g; cvta.to.global.u64 g, %1; cp.async.cg.shared.global [%0], [g], 16; }"
      ::"r"(dst), "l"(src) : "memory");
}
#define CP_COMMIT() asm volatile("cp.async.commit_group;" ::: "memory")
#define CP_WAIT(n) asm volatile("cp.async.wait_group %0;" ::"n"(n) : "memory")

// ---------------- pre-pass: convert K and V to fp16 -------------------------
__global__ void conv_kv_kernel(const float4* __restrict__ k4,
                               const float4* __restrict__ v4, int n4) {
  int i = blockIdx.x * blockDim.x + threadIdx.x;
  if (i >= n4) return;
  float4 kv = k4[i], vv = v4[i];
  g_kh[i * 2] = cvt_h2(kv.x, kv.y);
  g_kh[i * 2 + 1] = cvt_h2(kv.z, kv.w);
  g_vh[i * 2] = cvt_h2(vv.x, vv.y);
  g_vh[i * 2 + 1] = cvt_h2(vv.z, vv.w);
}

// ---------------- main flash-attention kernel -------------------------------
__global__ __launch_bounds__(NTHREADS, 3)
void fa_hmma_kernel(const float* __restrict__ q, const int* __restrict__ cu,
                    float* __restrict__ out, int T, int B) {
  extern __shared__ __align__(16) char smem[];
  const uint32_t smb = smem_u32(smem);
  const int tid = threadIdx.x, lane = tid & 31, wid = tid >> 5;
  const int g = lane >> 2, t = lane & 3;
  const int q0 = blockIdx.x * BM, h = blockIdx.y, hk = h / REP;
  const int wrow = wid * 16;

  // ---- per-thread row bounds ---------------------------------------------------
  const int r0 = q0 + wrow + g, r1 = r0 + 8;
  int rs0 = 0, rs1 = 0, kv_lo = 0;
  for (int b = 1; b <= B; b++) {
    int e = cu[b];
    if (r0 >= e) rs0 = e;
    if (r1 >= e) rs1 = e;
    if (q0 >= e) kv_lo = e;
  }
  const int hb0 = (r0 < T) ? r0 : -1;
  const int hb1 = (r1 < T) ? r1 : -1;
  const int kv_hi = min(q0 + BM, T);

  // staging decomposition (16 cp16/thread per tile: both K and V)
  const int sc = tid & 15, srh = tid >> 4;  // srh in 0..7

  auto stage = [&](int c0, int buf) {
    uint32_t dbase = smb + buf * BUFSZ;
#pragma unroll
    for (int i = 0; i < 16; i++) {
      int a = i >> 3;
      int r = (i & 7) * 8 + srh;
      const uint32_t* src =
          (a ? g_vh : g_kh) + ((size_t)(c0 + r) * KVH + hk) * (DIM / 2) + sc * 4;
      cp16(dbase + a * TILEB + (uint32_t)r * ROWB + sc * 16, src);
    }
    CP_COMMIT();
  };

  // ---- prefetch tile 0 into buf0; stage Q via buf1; hoist Q frags to regs -------
  stage(kv_lo, 0);

  const float4* q4 = reinterpret_cast<const float4*>(q);
#pragma unroll
  for (int it = 0; it < 16; it++) {
    int idx = it * NTHREADS + tid;
    int row = idx >> 5, c4 = idx & 31;
    float4 val = make_float4(0.f, 0.f, 0.f, 0.f);
    int gr = q0 + row;
    if (gr < T) val = q4[((size_t)gr * HEADS + h) * 32 + c4];
    uint32_t hi0 = cvt_h2(val.x * SCALE_L2E, val.y * SCALE_L2E);
    uint32_t hi1 = cvt_h2(val.z * SCALE_L2E, val.w * SCALE_L2E);
    uint32_t off = (uint32_t)row * ROWB + c4 * 8;
    *reinterpret_cast<uint2*>(smem + BUFSZ + off) = make_uint2(hi0, hi1);
  }
  __syncthreads();

  const uint32_t qstg = smb + BUFSZ +
                        ((uint32_t)(wrow + (lane & 7) + (((lane >> 3) & 1) << 3)) * ROWB) +
                        ((lane >> 4) << 4);
  uint32_t qh[8][4];
#pragma unroll
  for (int kt = 0; kt < 8; kt++) ldsm4(qstg + kt * 32, qh[kt]);

  // ---- ldmatrix per-thread base offsets for K/V ----------------------------------
  const uint32_t krow = ((uint32_t)((lane & 7) + ((lane >> 4) << 3)) * ROWB) +
                        (((lane >> 3) & 1) << 4);
  const uint32_t vrow = ((uint32_t)((lane & 7) + (((lane >> 3) & 1) << 3)) * ROWB) +
                        ((lane >> 4) << 4);

  float O[16][4];
#pragma unroll
  for (int i = 0; i < 16; i++)
#pragma unroll
    for (int j = 0; j < 4; j++) O[i][j] = 0.f;
  float l0 = 0.f, l1 = 0.f;

  int bi = 0;
  for (int c0 = kv_lo; c0 < kv_hi; c0 += BN, bi++) {
    const int buf = bi & 1;
    const bool has_next = (c0 + BN) < kv_hi;

    __syncthreads();  // readers of buf^1 done (bi=0: Q frag reads done)
    if (has_next) { stage(c0 + BN, buf ^ 1); CP_WAIT(1); }
    else          { CP_WAIT(0); }
    __syncthreads();  // current buffer visible to all warps

    const uint32_t bb = smb + buf * BUFSZ;
    const uint32_t kbase = bb + krow;          // KH
    const uint32_t vbase = bb + TILEB + vrow;  // VH

    // ---- S' = Q K^T (software-pipelined: ldsm for i+1 precedes MMAs of i) ----------
    float S[8][4];
#pragma unroll
    for (int i = 0; i < 8; i++)
#pragma unroll
      for (int j = 0; j < 4; j++) S[i][j] = 0.f;

    {
      uint32_t kf[2][4];
      ldsm4(kbase, kf[0]);  // it=0: kt=0, nt2=0
#pragma unroll
      for (int it = 0; it < 32; it++) {
        const int kt = it >> 2, nt2 = it & 3;
        if (it + 1 < 32) {
          const int nkt = (it + 1) >> 2, nnt2 = (it + 1) & 3;
          ldsm4(kbase + (uint32_t)nnt2 * (16 * ROWB) + nkt * 32, kf[(it + 1) & 1]);
        }
        mma_f16(S[2 * nt2], qh[kt], kf[it & 1][0], kf[it & 1][1]);
        mma_f16(S[2 * nt2 + 1], qh[kt], kf[it & 1][2], kf[it & 1][3]);
      }
    }

    // ---- softmax: p = 2^(S'), mask, round to fp16; l-sums from fp32 p --------------
    uint32_t Ph[4][4];
    const bool safe = (r1 < T) && (c0 >= rs1) && (c0 + BN <= r0 + 1);
    if (__all_sync(0xffffffffu, safe)) {
#pragma unroll
      for (int nt = 0; nt < 8; nt++) {
        float p0 = ex2(S[nt][0]);
        float p1 = ex2(S[nt][1]);
        float p2 = ex2(S[nt][2]);
        float p3 = ex2(S[nt][3]);
        l0 += p0 + p1;
        l1 += p2 + p3;
        int ktp = nt >> 1, s2 = (nt & 1) * 2;
        Ph[ktp][s2 + 0] = cvt_h2(p0, p1);
        Ph[ktp][s2 + 1] = cvt_h2(p2, p3);
      }
    } else {
#pragma unroll
      for (int nt = 0; nt < 8; nt++) {
        int cb = c0 + 8 * nt + 2 * t;
        float p0 = (cb >= rs0 && cb <= hb0) ? ex2(S[nt][0]) : 0.f;
        float p1 = (cb + 1 >= rs0 && cb + 1 <= hb0) ? ex2(S[nt][1]) : 0.f;
        float p2 = (cb >= rs1 && cb <= hb1) ? ex2(S[nt][2]) : 0.f;
        float p3 = (cb + 1 >= rs1 && cb + 1 <= hb1) ? ex2(S[nt][3]) : 0.f;
        l0 += p0 + p1;
        l1 += p2 + p3;
        int ktp = nt >> 1, s2 = (nt & 1) * 2;
        Ph[ktp][s2 + 0] = cvt_h2(p0, p1);
        Ph[ktp][s2 + 1] = cvt_h2(p2, p3);
      }
    }

    // ---- O += P V (software-pipelined ldmatrix.trans) -------------------------------
    {
      uint32_t vf[2][4];
      ldsm4t(vbase, vf[0]);  // it=0: ktp=0, d2=0
#pragma unroll
      for (int it = 0; it < 32; it++) {
        const int ktp = it >> 3, d2 = it & 7;
        if (it + 1 < 32) {
          const int nktp = (it + 1) >> 3, nd2 = (it + 1) & 7;
          ldsm4t(vbase + (uint32_t)nktp * (16 * ROWB) + nd2 * 32, vf[(it + 1) & 1]);
        }
        mma_f16(O[2 * d2], Ph[ktp], vf[it & 1][0], vf[it & 1][1]);
        mma_f16(O[2 * d2 + 1], Ph[ktp], vf[it & 1][2], vf[it & 1][3]);
      }
    }
  }

  // ---- epilogue: reduce row sums, normalize, store ---------------------------------
  l0 += __shfl_xor_sync(0xffffffffu, l0, 1);
  l0 += __shfl_xor_sync(0xffffffffu, l0, 2);
  l1 += __shfl_xor_sync(0xffffffffu, l1, 1);
  l1 += __shfl_xor_sync(0xffffffffu, l1, 2);
  const float inv0 = l0 > 0.f ? 1.0f / l0 : 0.f;
  const float inv1 = l1 > 0.f ? 1.0f / l1 : 0.f;

  if (r0 < T) {
    float* o0 = out + ((size_t)r0 * HEADS + h) * DIM + 2 * t;
#pragma unroll
    for (int nt = 0; nt < 16; nt++)
      *reinterpret_cast<float2*>(o0 + 8 * nt) = make_float2(O[nt][0] * inv0, O[nt][1] * inv0);
  }
  if (r1 < T) {
    float* o1 = out + ((size_t)r1 * HEADS + h) * DIM + 2 * t;
#pragma unroll
    for (int nt = 0; nt < 16; nt++)
      *reinterpret_cast<float2*>(o1 + 8 * nt) = make_float2(O[nt][2] * inv1, O[nt][3] * inv1);
  }
}

extern "C" void kernel_launch(void* const* d_in, const int* in_sizes, int n_in,
                              void* d_out, int out_size) {
  const float* q = (const float*)d_in[0];
  const float* k = (const float*)d_in[1];
  const float* v = (const float*)d_in[2];
  const int* cu = (const int*)d_in[3];
  float* out = (float*)d_out;

  const int T = in_sizes[0] / (HEADS * DIM);
  const int B = in_sizes[3] - 1;

  // pre-pass: convert K/V to persistent fp16 arrays
  const int n4 = T * KVH * DIM / 4;
  conv_kv_kernel<<<(n4 + 255) / 256, 256>>>(
      reinterpret_cast<const float4*>(k), reinterpret_cast<const float4*>(v), n4);

  cudaFuncSetAttribute(fa_hmma_kernel, cudaFuncAttributeMaxDynamicSharedMemorySize,
                       SMEM_TOTAL);
  dim3 grid((T + BM - 1) / BM, HEADS);
  fa_hmma_kernel<<<grid, NTHREADS, SMEM_TOTAL>>>(q, cu, out, T, B);
}